// round 15
// baseline (speedup 1.0000x reference)
#include <cuda_runtime.h>
#include <math.h>

#define BB 512
#define PP 256
#define TT 128
#define VV 10000
#define EE 300
#define HH 256
#define NCC 64
#define NOO 256
#define BN_EPS 1e-5f
#define NITEMS ((TT-1)*BB)          // 65024
#define HEAD_ITEMS 32               // items per head block (shared W)
#define ITEM_CAP (NITEMS + NCC*HEAD_ITEMS)  // 67072
#define NBLK 128                    // persistent grid size (<=148 SMs -> co-resident)

#define WSTRIDE 258                 // [u][k] weight row stride: 8B-aligned, conflict-free 64b LDS
#define WGSZ (32 * WSTRIDE)         // 8256 floats per gate slice
#define ASTRIDE 260                 // activation tile row stride: 16B-aligned float4 loads

typedef unsigned long long u64t;
#define UNPACK2(lo, hi, s) asm("mov.b64 {%0, %1}, %2;" : "=f"(lo), "=f"(hi) : "l"(s))
#define PACK2(d, lo, hi) asm("mov.b64 %0, {%1, %2};" : "=l"(d) : "f"(lo), "f"(hi))
#define FFMA2(d, a, b) asm("fma.rn.f32x2 %0, %1, %2, %0;" : "+l"(d) : "l"(a), "l"(b))
#define ADD2(d, o) asm("add.rn.f32x2 %0, %0, %1;" : "+l"(d) : "l"(o))

// ---------------- device scratch (no cudaMalloc allowed) ----------------
__device__ float g_encT[VV * 4 * HH];        // token -> lstm gate_x (+b_ih+b_hh)
__device__ float g_chT[NCC * NOO * 3 * HH];  // (prev,val) -> gru gx part
__device__ float g_idxT[NCC * 3 * HH];       // prev -> gru gx part
__device__ float g_progW[BB * 3 * HH];       // per-sample gx part (+b_ih)
__device__ float g_hA[BB * HH];
__device__ float g_hB[BB * HH];
__device__ float g_hall[(TT - 1) * BB * HH]; // all decoder hidden states
__device__ float g_psums[TT * 16 * HH * 2];  // BN partials [t][rowblk][feat][{s,s2}]
__device__ int   g_counts[NCC], g_offs[NCC], g_curs[NCC];
__device__ int   g_items[ITEM_CAP];
__device__ unsigned int g_bar_lstm[16];      // per-row-group barriers (8 blocks each)
__device__ unsigned int g_bar_gru;

__device__ __forceinline__ float sigm(float x) { return 1.f / (1.f + expf(-x)); }

// split monotonic-counter barrier (graph-replay safe); prefetch work goes between
__device__ __forceinline__ unsigned int bar_arrive(unsigned int* cnt) {
    __threadfence();
    __syncthreads();
    unsigned int a = 0;
    if (threadIdx.x == 0) a = atomicAdd(cnt, 1u) + 1u;
    return a;   // valid in thread 0 only
}
__device__ __forceinline__ void bar_wait(unsigned int* cnt, unsigned int nb, unsigned int a) {
    if (threadIdx.x == 0) {
        unsigned int target = ((a + nb - 1u) / nb) * nb;
        while (*((volatile unsigned int*)cnt) < target) { __nanosleep(20); }
    }
    __syncthreads();
}

// L2-only (L1-bypass) loads: cross-block data inside persistent kernels
__device__ __forceinline__ float4 ldcg4(const float* p) {
    return __ldcg(reinterpret_cast<const float4*>(p));
}
__device__ __forceinline__ float2 ldcg2(const float* p) {
    return __ldcg(reinterpret_cast<const float2*>(p));
}

// ---------------- init: zero output, reset binning scratch ----------------
__global__ __launch_bounds__(256) void init_kernel(float* __restrict__ out, int outN) {
    int stride = gridDim.x * blockDim.x;
    for (int idx = blockIdx.x * blockDim.x + threadIdx.x; idx < outN; idx += stride) {
        out[idx] = 0.f;
        if (idx < ITEM_CAP) g_items[idx] = -1;
        if (idx < NCC) { g_counts[idx] = 0; g_curs[idx] = 0; }
    }
}

// BN stats for decoder step 0 (from h_dec0), deterministic per-rowblock partials
__global__ __launch_bounds__(256) void stats0_kernel(const float* __restrict__ hdec0) {
    int by = blockIdx.x;
    int f = threadIdx.x;
    float s = 0.f, s2 = 0.f;
    for (int r = 0; r < 32; r++) {
        float v = hdec0[(by * 32 + r) * HH + f];
        s += v; s2 += v * v;
    }
    g_psums[((0 * 16 + by) * HH + f) * 2 + 0] = s;
    g_psums[((0 * 16 + by) * HH + f) * 2 + 1] = s2;
}

// ---------------- C = A(MxK) * B(NxK)^T + bias0 + bias1 (dst via selector) ----------------
__global__ __launch_bounds__(256) void gemm_nt(const float* __restrict__ Aext, int lda,
                                               const float* __restrict__ Bm, int ldb,
                                               const float* __restrict__ bias0,
                                               const float* __restrict__ bias1,
                                               int M, int N, int K, int dst_id, int src_hB) {
    const float* A = src_hB ? g_hB : Aext;
    float* C = (dst_id == 0) ? g_encT : (dst_id == 1) ? g_chT : (dst_id == 2) ? g_idxT : g_progW;
    __shared__ float As[16][68];
    __shared__ float Bs[16][68];
    int tid = threadIdx.x;
    int tx = tid & 15, ty = tid >> 4;
    int m0 = blockIdx.y * 64, n0 = blockIdx.x * 64;
    u64t acc2[2][4];
#pragma unroll
    for (int i = 0; i < 2; i++)
#pragma unroll
        for (int j = 0; j < 4; j++) acc2[i][j] = 0ull;

    for (int k0 = 0; k0 < K; k0 += 16) {
#pragma unroll
        for (int p = 0; p < 4; p++) {
            int l = tid + p * 256;
            int row = l >> 4, kk = l & 15;
            int k = k0 + kk;
            int m = m0 + row;
            As[kk][row] = (m < M && k < K) ? A[m * lda + k] : 0.f;
            int n = n0 + row;
            Bs[kk][row] = (n < N && k < K) ? Bm[n * ldb + k] : 0.f;
        }
        __syncthreads();
#pragma unroll
        for (int kk = 0; kk < 16; kk++) {
            u64t a01 = *(const u64t*)&As[kk][ty * 4];
            u64t a23 = *(const u64t*)&As[kk][ty * 4 + 2];
            float4 b4 = *(const float4*)&Bs[kk][tx * 4];
            const float* bp = (const float*)&b4;
#pragma unroll
            for (int j = 0; j < 4; j++) {
                u64t b2;
                PACK2(b2, bp[j], bp[j]);
                FFMA2(acc2[0][j], a01, b2);
                FFMA2(acc2[1][j], a23, b2);
            }
        }
        __syncthreads();
    }
#pragma unroll
    for (int ip = 0; ip < 2; ip++) {
#pragma unroll
        for (int j = 0; j < 4; j++) {
            float vlo, vhi;
            UNPACK2(vlo, vhi, acc2[ip][j]);
            int n = n0 + tx * 4 + j;
            if (n >= N) continue;
            float badd = (bias0 ? bias0[n] : 0.f) + (bias1 ? bias1[n] : 0.f);
            int mA = m0 + ty * 4 + ip * 2;
            if (mA < M) C[mA * N + n] = vlo + badd;
            if (mA + 1 < M) C[(mA + 1) * N + n] = vhi + badd;
        }
    }
}

// ---------------- persistent LSTM: k-split (8 rows/thread per k-half) ----------------
// grid 128 = (8 u-tiles) x (16 row-groups); block 256 = 32 tx(u) x [rh 0..3][kh 0..1].
// Weight LDS amortized over 8 rows -> crossbar ~6.1K cyc/step < fma 8.2K (was 12.3K).
__global__ __launch_bounds__(256, 1) void lstm_persist(const float* __restrict__ Whh,
                                                       const int* __restrict__ program,
                                                       const int* __restrict__ plen,
                                                       const float* __restrict__ h0,
                                                       const float* __restrict__ c0) {
    extern __shared__ float sm[];
    float* Wsh = sm;                    // [4][32][WSTRIDE] = 33024 floats
    float* At = sm + 4 * WGSZ;          // [32][ASTRIDE] = 8320 floats; also k-half reduce buf

    int tid = threadIdx.x;
    int tx = tid & 31;
    int ty = tid >> 5;                  // 0..7
    int rh = ty & 3;                    // rows rh*8 .. rh*8+7
    int kh = ty >> 2;                   // k-half
    int u0 = (blockIdx.x & 7) * 32;
    int ry = blockIdx.x >> 3;
    int r0 = ry * 32;
    int u = u0 + tx;

    for (int idx = tid; idx < 4 * 32 * 256; idx += 256) {
        int k = idx & 255;
        int uu = (idx >> 8) & 31;
        int g = idx >> 13;
        Wsh[g * WGSZ + uu * WSTRIDE + k] = Whh[(g * HH + u0 + uu) * HH + k];
    }

    float h_reg[8], c_reg[8];
    int pl[8];
    if (kh == 0) {
#pragma unroll
        for (int r = 0; r < 8; r++) {
            int R = r0 + rh * 8 + r;
            h_reg[r] = h0[R * HH + u];
            c_reg[r] = c0[R * HH + u];
            pl[r] = plen[R];
        }
    }
    __syncthreads();

    const float* wrow = Wsh + tx * WSTRIDE;
    const int kbase = kh * 128;

    float gx0[8], gx1[8], gx2[8], gx3[8];
    if (kh == 0) {
#pragma unroll
        for (int r = 0; r < 8; r++) {
            int R = r0 + rh * 8 + r;
            int tok = program[R * PP + 0];
            const float* gp = g_encT + (size_t)tok * (4 * HH) + u;
            gx0[r] = __ldg(gp); gx1[r] = __ldg(gp + HH);
            gx2[r] = __ldg(gp + 2 * HH); gx3[r] = __ldg(gp + 3 * HH);
        }
    }

    for (int t = 0; t < PP; t++) {
        const float* hin = (t == 0) ? h0 : ((t & 1) ? g_hA : g_hB);
        float* hout = (t & 1) ? g_hB : g_hA;

        // whole 32x256 activation tile -> smem (float4 .cg, coalesced)
#pragma unroll
        for (int p = 0; p < 8; p++) {
            int l = tid + p * 256;
            int row = l >> 6, c4 = (l & 63) << 2;
            float4 v = ldcg4(&hin[(r0 + row) * HH + c4]);
            *(float4*)&At[row * ASTRIDE + c4] = v;
        }
        __syncthreads();

        u64t acc2[32];   // [g*8+r], k-pair lane sums over this thread's k-half
#pragma unroll
        for (int j = 0; j < 32; j++) acc2[j] = 0ull;

#pragma unroll 4
        for (int kk = 0; kk < 128; kk += 4) {
            float4 a4[8];
#pragma unroll
            for (int r = 0; r < 8; r++)
                a4[r] = *(const float4*)&At[(rh * 8 + r) * ASTRIDE + kbase + kk];
#pragma unroll
            for (int p = 0; p < 2; p++) {
#pragma unroll
                for (int g = 0; g < 4; g++) {
                    u64t w2 = *(const u64t*)(wrow + g * WGSZ + kbase + kk + 2 * p);
#pragma unroll
                    for (int r = 0; r < 8; r++) {
                        u64t a2 = ((const u64t*)&a4[r])[p];
                        FFMA2(acc2[g * 8 + r], a2, w2);
                    }
                }
            }
        }

        // k-half reduction: kh=1 stores (xor-swizzled, conflict-free), kh=0 accumulates
        __syncthreads();
        {
            u64t* red = (u64t*)At;
            int idx = rh * 32 + tx;
            if (kh == 1) {
#pragma unroll
                for (int j = 0; j < 32; j++)
                    red[(size_t)idx * 32 + (j ^ tx)] = acc2[j];
            }
        }
        __syncthreads();

        if (kh == 0) {
            u64t* red = (u64t*)At;
            int idx = rh * 32 + tx;
#pragma unroll
            for (int j = 0; j < 32; j++) {
                u64t o = red[(size_t)idx * 32 + (j ^ tx)];
                ADD2(acc2[j], o);
            }
#pragma unroll
            for (int r = 0; r < 8; r++) {
                float lo, hi;
                UNPACK2(lo, hi, acc2[0 * 8 + r]); float vi = lo + hi;
                UNPACK2(lo, hi, acc2[1 * 8 + r]); float vf = lo + hi;
                UNPACK2(lo, hi, acc2[2 * 8 + r]); float vg = lo + hi;
                UNPACK2(lo, hi, acc2[3 * 8 + r]); float vo = lo + hi;
                int R = r0 + rh * 8 + r;
                float ig = sigm(vi + gx0[r]);
                float fg = sigm(vf + gx1[r]);
                float gg = tanhf(vg + gx2[r]);
                float og = sigm(vo + gx3[r]);
                float cnew = fg * c_reg[r] + ig * gg;
                float hnew = og * tanhf(cnew);
                bool valid = t < pl[r];
                float cv = valid ? cnew : c_reg[r];
                float hv = valid ? hnew : h_reg[r];
                c_reg[r] = cv;
                h_reg[r] = hv;
                __stcg(&hout[R * HH + u], hv);
            }
        }

        unsigned int a = bar_arrive(&g_bar_lstm[ry]);
        if (kh == 0 && t + 1 < PP) {
#pragma unroll
            for (int r = 0; r < 8; r++) {
                int R = r0 + rh * 8 + r;
                int tok = program[R * PP + t + 1];
                const float* gp = g_encT + (size_t)tok * (4 * HH) + u;
                gx0[r] = __ldg(gp); gx1[r] = __ldg(gp + HH);
                gx2[r] = __ldg(gp + 2 * HH); gx3[r] = __ldg(gp + 3 * HH);
            }
        }
        bar_wait(&g_bar_lstm[ry], 8u, a);
    }
}

// ---------------- persistent GRU: k-split, BN fused into tile load ----------------
__global__ __launch_bounds__(256, 1) void gru_persist(const float* __restrict__ Whh,
                                                      const float* __restrict__ bhh,
                                                      const float* __restrict__ gamma,
                                                      const float* __restrict__ beta,
                                                      const int* __restrict__ trace,
                                                      const int* __restrict__ choices,
                                                      const float* __restrict__ hdec0) {
    extern __shared__ float sm[];
    float* Wsh = sm;                        // [3][32][WSTRIDE] = 24768
    float* At = sm + 3 * WGSZ;              // [32][ASTRIDE] = 8320; also reduce buf
    float* s_sc = At + 32 * ASTRIDE;        // [256]
    float* s_sh = s_sc + HH;                // [256]
    float* psbuf = s_sh + HH;               // [256]: ps[rh*32+tx], ps2[128+rh*32+tx]

    int tid = threadIdx.x;
    int tx = tid & 31;
    int ty = tid >> 5;
    int rh = ty & 3;
    int kh = ty >> 2;
    int u0 = (blockIdx.x & 7) * 32;
    int ry = blockIdx.x >> 3;
    int r0 = ry * 32;
    int u = u0 + tx;

    for (int idx = tid; idx < 3 * 32 * 256; idx += 256) {
        int k = idx & 255;
        int uu = (idx >> 8) & 31;
        int g = idx >> 13;
        Wsh[g * WGSZ + uu * WSTRIDE + k] = Whh[(g * HH + u0 + uu) * HH + k];
    }

    float bh0 = bhh[u], bh1 = bhh[HH + u], bh2 = bhh[2 * HH + u];
    float gmv = gamma[tid], btv = beta[tid];

    float h_reg[8];
    if (kh == 0) {
#pragma unroll
        for (int r = 0; r < 8; r++) h_reg[r] = hdec0[(r0 + rh * 8 + r) * HH + u];
    }
    __syncthreads();

    const float* wrow = Wsh + tx * WSTRIDE;
    const int kbase = kh * 128;

    for (int t = 0; t < TT - 1; t++) {
        const float* hin = (t == 0) ? hdec0 : (g_hall + (size_t)(t - 1) * BB * HH);
        float* hout = g_hall + (size_t)t * BB * HH;

        // routed-table gathers, summed immediately (24 live regs, not 72)
        float gxr[8], gxz[8], gxn[8];
        if (kh == 0) {
#pragma unroll
            for (int r = 0; r < 8; r++) {
                int R = r0 + rh * 8 + r;
                int prev = trace[R * TT + t];
                int val = choices[R * NCC + prev];
                const float* pw = g_progW + (size_t)R * (3 * HH) + u;
                const float* iw = g_idxT + (size_t)prev * (3 * HH) + u;
                const float* cw = g_chT + (size_t)(prev * NOO + val) * (3 * HH) + u;
                gxr[r] = __ldg(pw) + __ldg(iw) + __ldg(cw);
                gxz[r] = __ldg(pw + HH) + __ldg(iw + HH) + __ldg(cw + HH);
                gxn[r] = __ldg(pw + 2 * HH) + __ldg(iw + 2 * HH) + __ldg(cw + 2 * HH);
            }
        }

        // BN scale/shift from step-t partial sums (feature = tid, 64b paired loads)
        {
            float s = 0.f, s2 = 0.f;
#pragma unroll
            for (int p = 0; p < 16; p++) {
                float2 pv = ldcg2(&g_psums[((t * 16 + p) * HH + tid) * 2]);
                s += pv.x; s2 += pv.y;
            }
            float mean = s * (1.f / (float)BB);
            float var = fmaxf(s2 * (1.f / (float)BB) - mean * mean, 0.f);
            float inv = rsqrtf(var + BN_EPS);
            float scv = gmv * inv;
            s_sc[tid] = scv;
            s_sh[tid] = btv - mean * scv;
        }
        __syncthreads();

        // whole 32x256 tile, BN applied inline (L1-bypass loads)
#pragma unroll
        for (int p = 0; p < 8; p++) {
            int l = tid + p * 256;
            int row = l >> 6, c4 = (l & 63) << 2;
            float4 v = ldcg4(&hin[(r0 + row) * HH + c4]);
            v.x = v.x * s_sc[c4 + 0] + s_sh[c4 + 0];
            v.y = v.y * s_sc[c4 + 1] + s_sh[c4 + 1];
            v.z = v.z * s_sc[c4 + 2] + s_sh[c4 + 2];
            v.w = v.w * s_sc[c4 + 3] + s_sh[c4 + 3];
            *(float4*)&At[row * ASTRIDE + c4] = v;
        }
        __syncthreads();

        u64t acc2[24];   // [g*8+r]
#pragma unroll
        for (int j = 0; j < 24; j++) acc2[j] = 0ull;

#pragma unroll 4
        for (int kk = 0; kk < 128; kk += 4) {
            float4 a4[8];
#pragma unroll
            for (int r = 0; r < 8; r++)
                a4[r] = *(const float4*)&At[(rh * 8 + r) * ASTRIDE + kbase + kk];
#pragma unroll
            for (int p = 0; p < 2; p++) {
#pragma unroll
                for (int g = 0; g < 3; g++) {
                    u64t w2 = *(const u64t*)(wrow + g * WGSZ + kbase + kk + 2 * p);
#pragma unroll
                    for (int r = 0; r < 8; r++) {
                        u64t a2 = ((const u64t*)&a4[r])[p];
                        FFMA2(acc2[g * 8 + r], a2, w2);
                    }
                }
            }
        }

        __syncthreads();
        {
            u64t* red = (u64t*)At;
            int idx = rh * 32 + tx;
            if (kh == 1) {
#pragma unroll
                for (int j = 0; j < 24; j++)
                    red[(size_t)idx * 32 + (j ^ tx)] = acc2[j];
            }
        }
        __syncthreads();

        if (kh == 0) {
            u64t* red = (u64t*)At;
            int idx = rh * 32 + tx;
#pragma unroll
            for (int j = 0; j < 24; j++) {
                u64t o = red[(size_t)idx * 32 + (j ^ tx)];
                ADD2(acc2[j], o);
            }
            float scu = s_sc[u], shu = s_sh[u];
            float ps = 0.f, ps2 = 0.f;
#pragma unroll
            for (int r = 0; r < 8; r++) {
                float lo, hi;
                UNPACK2(lo, hi, acc2[0 * 8 + r]); float vr = lo + hi;
                UNPACK2(lo, hi, acc2[1 * 8 + r]); float vz = lo + hi;
                UNPACK2(lo, hi, acc2[2 * 8 + r]); float vn = lo + hi;
                int R = r0 + rh * 8 + r;
                float rr = sigm(gxr[r] + vr + bh0);
                float zz = sigm(gxz[r] + vz + bh1);
                float nn = tanhf(gxn[r] + rr * (vn + bh2));
                float hnb = h_reg[r] * scu + shu;
                float hnew = (1.f - zz) * nn + zz * hnb;
                h_reg[r] = hnew;
                __stcg(&hout[R * HH + u], hnew);
                ps += hnew;
                ps2 += hnew * hnew;
            }
            psbuf[rh * 32 + tx] = ps;
            psbuf[128 + rh * 32 + tx] = ps2;
        }

        // deterministic BN partials for step t+1
        __syncthreads();
        if (ty == 0) {
            float s  = psbuf[tx] + psbuf[32 + tx] + psbuf[64 + tx] + psbuf[96 + tx];
            float s2 = psbuf[128 + tx] + psbuf[160 + tx] + psbuf[192 + tx] + psbuf[224 + tx];
            float2 pv = make_float2(s, s2);
            __stcg(reinterpret_cast<float2*>(&g_psums[(((t + 1) * 16 + ry) * HH + u) * 2]), pv);
        }

        unsigned int a = bar_arrive(&g_bar_gru);
        bar_wait(&g_bar_gru, NBLK, a);
    }
}

// ---------------- head binning (coalesced: i = b*127 + t, lanes walk t) ----------------
__global__ __launch_bounds__(256) void count_kernel(const int* __restrict__ trace) {
    int i = blockIdx.x * 256 + threadIdx.x;
    if (i >= NITEMS) return;
    int b = i / (TT - 1), t = i - b * (TT - 1);
    int c = trace[b * TT + t + 1];
    if (c != 0) atomicAdd(&g_counts[c], 1);
}

__global__ void prefix_kernel() {
    if (threadIdx.x == 0) {
        int off = 0;
        for (int c = 0; c < NCC; c++) {
            g_offs[c] = off;
            off += ((g_counts[c] + HEAD_ITEMS - 1) / HEAD_ITEMS) * HEAD_ITEMS;
        }
    }
}

__global__ __launch_bounds__(256) void scatter_kernel(const int* __restrict__ trace) {
    int i = blockIdx.x * 256 + threadIdx.x;
    if (i >= NITEMS) return;
    int b = i / (TT - 1), t = i - b * (TT - 1);
    int c = trace[b * TT + t + 1];
    if (c != 0) {
        int pos = g_offs[c] + atomicAdd(&g_curs[c], 1);
        g_items[pos] = (t << 16) | b;
    }
}

// ---------------- routed head: 32 items per block share one 256x256 W (k-pair f32x2) ----------------
__global__ __launch_bounds__(256) void head_kernel(const int* __restrict__ trace,
                                                   const float* __restrict__ infW,
                                                   const float* __restrict__ infB,
                                                   float* __restrict__ out) {
    __shared__ int sIt[HEAD_ITEMS];
    __shared__ float Hs[HEAD_ITEMS][32];
    __shared__ float Ws[256 * 34];
    int tid = threadIdx.x;
    if (tid < HEAD_ITEMS) sIt[tid] = g_items[blockIdx.x * HEAD_ITEMS + tid];
    __syncthreads();
    int it0 = sIt[0];
    if (it0 < 0) return;
    int t0 = it0 >> 16, b0 = it0 & 0xFFFF;
    int c = trace[b0 * TT + t0 + 1];
    const float* W = infW + (size_t)c * NOO * HH;

    u64t acc2[HEAD_ITEMS];
#pragma unroll
    for (int i = 0; i < HEAD_ITEMS; i++) acc2[i] = 0ull;
    int o = tid;
    const float* wrow = Ws + o * 34;

    for (int k0 = 0; k0 < HH; k0 += 32) {
        for (int l = tid; l < HEAD_ITEMS * 32; l += 256) {
            int i = l >> 5, kk = l & 31;
            int it = sIt[i];
            float v = 0.f;
            if (it >= 0) {
                int tt = it >> 16, bb = it & 0xFFFF;
                v = g_hall[((size_t)tt * BB + bb) * HH + k0 + kk];
            }
            Hs[i][kk] = v;
        }
#pragma unroll 8
        for (int l = tid; l < 8192; l += 256) {
            int oo = l >> 5, kk = l & 31;
            Ws[oo * 34 + kk] = W[oo * HH + k0 + kk];
        }
        __syncthreads();
#pragma unroll
        for (int kk = 0; kk < 32; kk += 2) {
            u64t w2 = *(const u64t*)(wrow + kk);
#pragma unroll
            for (int i = 0; i < HEAD_ITEMS; i++) {
                u64t h2 = *(const u64t*)&Hs[i][kk];
                FFMA2(acc2[i], h2, w2);
            }
        }
        __syncthreads();
    }

    float bias = infB[c * NOO + o];
#pragma unroll
    for (int i = 0; i < HEAD_ITEMS; i++) {
        int it = sIt[i];
        if (it >= 0) {
            float lo, hi;
            UNPACK2(lo, hi, acc2[i]);
            int tt = it >> 16, bb = it & 0xFFFF;
            out[((size_t)tt * BB + bb) * NOO + o] = lo + hi + bias;
        }
    }
}

// ---------------- launcher (lstm_persist placed as 6th launch for ncu -s 5 -c 1) ----------------
extern "C" void kernel_launch(void* const* d_in, const int* in_sizes, int n_in,
                              void* d_out, int out_size) {
    const int* program      = (const int*)d_in[0];
    const int* plen         = (const int*)d_in[1];
    const int* trace        = (const int*)d_in[2];
    const int* choices      = (const int*)d_in[3];
    const float* enc_embed  = (const float*)d_in[4];
    const float* lstm_W_ih  = (const float*)d_in[5];
    const float* lstm_W_hh  = (const float*)d_in[6];
    const float* lstm_b_ih  = (const float*)d_in[7];
    const float* lstm_b_hh  = (const float*)d_in[8];
    const float* h0         = (const float*)d_in[9];
    const float* c0         = (const float*)d_in[10];
    const float* index_embed= (const float*)d_in[11];
    const float* choice_tab = (const float*)d_in[12];
    const float* gru_W_ih   = (const float*)d_in[13];
    const float* gru_W_hh   = (const float*)d_in[14];
    const float* gru_b_ih   = (const float*)d_in[15];
    const float* gru_b_hh   = (const float*)d_in[16];
    const float* bn_gamma   = (const float*)d_in[17];
    const float* bn_beta    = (const float*)d_in[18];
    const float* inf_W      = (const float*)d_in[19];
    const float* inf_b      = (const float*)d_in[20];
    const float* h_dec0     = (const float*)d_in[21];
    float* out = (float*)d_out;

    const int LSTM_SMEM = (4 * WGSZ + 32 * ASTRIDE) * 4;                      // 165376 B
    const int GRU_SMEM  = (3 * WGSZ + 32 * ASTRIDE + 2 * HH + 256) * 4;       // 135424 B
    cudaFuncSetAttribute(lstm_persist, cudaFuncAttributeMaxDynamicSharedMemorySize, LSTM_SMEM);
    cudaFuncSetAttribute(gru_persist, cudaFuncAttributeMaxDynamicSharedMemorySize, GRU_SMEM);

    init_kernel<<<4096, 256>>>(out, out_size);                                     // 1
    stats0_kernel<<<16, 256>>>(h_dec0);                                            // 2

    gemm_nt<<<dim3(16, 157), 256>>>(enc_embed, EE, lstm_W_ih, EE,
                                    lstm_b_ih, lstm_b_hh, VV, 4 * HH, EE, 0, 0);   // 3: encT
    gemm_nt<<<dim3(12, 256), 256>>>(choice_tab, EE, gru_W_ih, HH + 2 * EE,
                                    nullptr, nullptr, NCC * NOO, 3 * HH, EE, 1, 0);// 4: chT
    gemm_nt<<<dim3(12, 1), 256>>>(index_embed, EE, gru_W_ih + (HH + EE), HH + 2 * EE,
                                  nullptr, nullptr, NCC, 3 * HH, EE, 2, 0);        // 5: idxT

    lstm_persist<<<NBLK, 256, LSTM_SMEM>>>(lstm_W_hh, program, plen, h0, c0);      // 6 (ncu target)

    gemm_nt<<<dim3(12, 8), 256>>>(nullptr, HH, gru_W_ih + EE, HH + 2 * EE,
                                  gru_b_ih, nullptr, BB, 3 * HH, HH, 3, 1);        // 7: progW

    count_kernel<<<(NITEMS + 255) / 256, 256>>>(trace);                            // 8
    prefix_kernel<<<1, 32>>>();                                                    // 9
    scatter_kernel<<<(NITEMS + 255) / 256, 256>>>(trace);                          // 10

    gru_persist<<<NBLK, 256, GRU_SMEM>>>(gru_W_hh, gru_b_hh, bn_gamma, bn_beta,
                                         trace, choices, h_dec0);                  // 11

    head_kernel<<<ITEM_CAP / HEAD_ITEMS, 256>>>(trace, inf_W, inf_b, out);         // 12
}

// round 16
// speedup vs baseline: 1.0001x; 1.0001x over previous
#include <cuda_runtime.h>
#include <math.h>

#define BB 512
#define PP 256
#define TT 128
#define VV 10000
#define EE 300
#define HH 256
#define NCC 64
#define NOO 256
#define BN_EPS 1e-5f
#define NITEMS ((TT-1)*BB)          // 65024
#define HEAD_ITEMS 32               // items per head block (shared W)
#define ITEM_CAP (NITEMS + NCC*HEAD_ITEMS)  // 67072
#define NBLK 128                    // persistent grid size (<=148 SMs -> co-resident)

#define WSTRIDE 258                 // [u][k] weight row stride: 8B-aligned, conflict-free 64b LDS
#define WGSZ (32 * WSTRIDE)         // 8256 floats per gate slice
#define ASTRIDE 260                 // activation tile row stride: 16B-aligned float4 loads

typedef unsigned long long u64t;
#define UNPACK2(lo, hi, s) asm("mov.b64 {%0, %1}, %2;" : "=f"(lo), "=f"(hi) : "l"(s))
#define PACK2(d, lo, hi) asm("mov.b64 %0, {%1, %2};" : "=l"(d) : "f"(lo), "f"(hi))
#define FFMA2(d, a, b) asm("fma.rn.f32x2 %0, %1, %2, %0;" : "+l"(d) : "l"(a), "l"(b))
#define ADD2(d, o) asm("add.rn.f32x2 %0, %0, %1;" : "+l"(d) : "l"(o))

// ---------------- device scratch (no cudaMalloc allowed) ----------------
__device__ float g_encT[VV * 4 * HH];        // token -> lstm gate_x (+b_ih+b_hh)
__device__ float g_chT[NCC * NOO * 3 * HH];  // (prev,val) -> gru gx part
__device__ float g_idxT[NCC * 3 * HH];       // prev -> gru gx part
__device__ float g_progW[BB * 3 * HH];       // per-sample gx part (+b_ih)
__device__ float g_hA[BB * HH];
__device__ float g_hB[BB * HH];
__device__ float g_hall[(TT - 1) * BB * HH]; // all decoder hidden states
__device__ float g_psums[TT * 16 * HH * 2];  // BN partials [t][rowblk][feat][{s,s2}]
__device__ int   g_counts[NCC], g_offs[NCC], g_curs[NCC];
__device__ int   g_items[ITEM_CAP];
__device__ unsigned int g_bar_lstm[16];      // per-row-group barriers (8 blocks each)
__device__ unsigned int g_gru_loc[16];       // GRU 2-level barrier: per-group arrivals
__device__ unsigned int g_gru_glob;          // GRU 2-level barrier: group-completion count

__device__ __forceinline__ float sigm(float x) { return 1.f / (1.f + expf(-x)); }

// split monotonic-counter barrier (graph-replay safe); prefetch work goes between
__device__ __forceinline__ unsigned int bar_arrive(unsigned int* cnt) {
    __threadfence();
    __syncthreads();
    unsigned int a = 0;
    if (threadIdx.x == 0) a = atomicAdd(cnt, 1u) + 1u;
    return a;   // valid in thread 0 only
}
__device__ __forceinline__ void bar_wait(unsigned int* cnt, unsigned int nb, unsigned int a) {
    if (threadIdx.x == 0) {
        unsigned int target = ((a + nb - 1u) / nb) * nb;
        while (*((volatile unsigned int*)cnt) < target) { __nanosleep(20); }
    }
    __syncthreads();
}

// GRU two-level full-grid barrier (16 groups x 8 blocks): parallel per-group
// arrival lines + 16 global events -> ~5x less atomic serialization.
__device__ __forceinline__ unsigned int glob_arrive(int ry) {
    __threadfence();
    __syncthreads();
    unsigned int r = 0;
    if (threadIdx.x == 0) {
        unsigned int a = atomicAdd(&g_gru_loc[ry], 1u) + 1u;
        if ((a & 7u) == 0u) atomicAdd(&g_gru_glob, 1u);   // group round complete
        r = (a + 7u) >> 3;                                // this block's round
    }
    return r;   // valid in thread 0 only
}
__device__ __forceinline__ void glob_wait(unsigned int r) {
    if (threadIdx.x == 0) {
        while (*((volatile unsigned int*)&g_gru_glob) < r * 16u) { __nanosleep(20); }
    }
    __syncthreads();
}

// L2-only (L1-bypass) loads: cross-block data inside persistent kernels
__device__ __forceinline__ float4 ldcg4(const float* p) {
    return __ldcg(reinterpret_cast<const float4*>(p));
}
__device__ __forceinline__ float2 ldcg2(const float* p) {
    return __ldcg(reinterpret_cast<const float2*>(p));
}

// ---------------- init: zero output, reset binning scratch ----------------
__global__ __launch_bounds__(256) void init_kernel(float* __restrict__ out, int outN) {
    int stride = gridDim.x * blockDim.x;
    for (int idx = blockIdx.x * blockDim.x + threadIdx.x; idx < outN; idx += stride) {
        out[idx] = 0.f;
        if (idx < ITEM_CAP) g_items[idx] = -1;
        if (idx < NCC) { g_counts[idx] = 0; g_curs[idx] = 0; }
    }
}

// BN stats for decoder step 0 (from h_dec0), deterministic per-rowblock partials
__global__ __launch_bounds__(256) void stats0_kernel(const float* __restrict__ hdec0) {
    int by = blockIdx.x;
    int f = threadIdx.x;
    float s = 0.f, s2 = 0.f;
    for (int r = 0; r < 32; r++) {
        float v = hdec0[(by * 32 + r) * HH + f];
        s += v; s2 += v * v;
    }
    g_psums[((0 * 16 + by) * HH + f) * 2 + 0] = s;
    g_psums[((0 * 16 + by) * HH + f) * 2 + 1] = s2;
}

// ---------------- C = A(MxK) * B(NxK)^T + bias0 + bias1 (dst via selector) ----------------
__global__ __launch_bounds__(256) void gemm_nt(const float* __restrict__ Aext, int lda,
                                               const float* __restrict__ Bm, int ldb,
                                               const float* __restrict__ bias0,
                                               const float* __restrict__ bias1,
                                               int M, int N, int K, int dst_id, int src_hB) {
    const float* A = src_hB ? g_hB : Aext;
    float* C = (dst_id == 0) ? g_encT : (dst_id == 1) ? g_chT : (dst_id == 2) ? g_idxT : g_progW;
    __shared__ float As[16][68];
    __shared__ float Bs[16][68];
    int tid = threadIdx.x;
    int tx = tid & 15, ty = tid >> 4;
    int m0 = blockIdx.y * 64, n0 = blockIdx.x * 64;
    u64t acc2[2][4];
#pragma unroll
    for (int i = 0; i < 2; i++)
#pragma unroll
        for (int j = 0; j < 4; j++) acc2[i][j] = 0ull;

    for (int k0 = 0; k0 < K; k0 += 16) {
#pragma unroll
        for (int p = 0; p < 4; p++) {
            int l = tid + p * 256;
            int row = l >> 4, kk = l & 15;
            int k = k0 + kk;
            int m = m0 + row;
            As[kk][row] = (m < M && k < K) ? A[m * lda + k] : 0.f;
            int n = n0 + row;
            Bs[kk][row] = (n < N && k < K) ? Bm[n * ldb + k] : 0.f;
        }
        __syncthreads();
#pragma unroll
        for (int kk = 0; kk < 16; kk++) {
            u64t a01 = *(const u64t*)&As[kk][ty * 4];
            u64t a23 = *(const u64t*)&As[kk][ty * 4 + 2];
            float4 b4 = *(const float4*)&Bs[kk][tx * 4];
            const float* bp = (const float*)&b4;
#pragma unroll
            for (int j = 0; j < 4; j++) {
                u64t b2;
                PACK2(b2, bp[j], bp[j]);
                FFMA2(acc2[0][j], a01, b2);
                FFMA2(acc2[1][j], a23, b2);
            }
        }
        __syncthreads();
    }
#pragma unroll
    for (int ip = 0; ip < 2; ip++) {
#pragma unroll
        for (int j = 0; j < 4; j++) {
            float vlo, vhi;
            UNPACK2(vlo, vhi, acc2[ip][j]);
            int n = n0 + tx * 4 + j;
            if (n >= N) continue;
            float badd = (bias0 ? bias0[n] : 0.f) + (bias1 ? bias1[n] : 0.f);
            int mA = m0 + ty * 4 + ip * 2;
            if (mA < M) C[mA * N + n] = vlo + badd;
            if (mA + 1 < M) C[(mA + 1) * N + n] = vhi + badd;
        }
    }
}

// ---------------- persistent LSTM: k-split (8 rows/thread per k-half) ----------------
// grid 128 = (8 u-tiles) x (16 row-groups); block 256 = 32 tx(u) x [rh 0..3][kh 0..1].
__global__ __launch_bounds__(256, 1) void lstm_persist(const float* __restrict__ Whh,
                                                       const int* __restrict__ program,
                                                       const int* __restrict__ plen,
                                                       const float* __restrict__ h0,
                                                       const float* __restrict__ c0) {
    extern __shared__ float sm[];
    float* Wsh = sm;                    // [4][32][WSTRIDE] = 33024 floats
    float* At = sm + 4 * WGSZ;          // [32][ASTRIDE] = 8320 floats; also k-half reduce buf

    int tid = threadIdx.x;
    int tx = tid & 31;
    int ty = tid >> 5;                  // 0..7
    int rh = ty & 3;                    // rows rh*8 .. rh*8+7
    int kh = ty >> 2;                   // k-half
    int u0 = (blockIdx.x & 7) * 32;
    int ry = blockIdx.x >> 3;
    int r0 = ry * 32;
    int u = u0 + tx;

    for (int idx = tid; idx < 4 * 32 * 256; idx += 256) {
        int k = idx & 255;
        int uu = (idx >> 8) & 31;
        int g = idx >> 13;
        Wsh[g * WGSZ + uu * WSTRIDE + k] = Whh[(g * HH + u0 + uu) * HH + k];
    }

    float h_reg[8], c_reg[8];
    int pl[8];
    if (kh == 0) {
#pragma unroll
        for (int r = 0; r < 8; r++) {
            int R = r0 + rh * 8 + r;
            h_reg[r] = h0[R * HH + u];
            c_reg[r] = c0[R * HH + u];
            pl[r] = plen[R];
        }
    }
    __syncthreads();

    const float* wrow = Wsh + tx * WSTRIDE;
    const int kbase = kh * 128;

    float gx0[8], gx1[8], gx2[8], gx3[8];
    if (kh == 0) {
#pragma unroll
        for (int r = 0; r < 8; r++) {
            int R = r0 + rh * 8 + r;
            int tok = program[R * PP + 0];
            const float* gp = g_encT + (size_t)tok * (4 * HH) + u;
            gx0[r] = __ldg(gp); gx1[r] = __ldg(gp + HH);
            gx2[r] = __ldg(gp + 2 * HH); gx3[r] = __ldg(gp + 3 * HH);
        }
    }

    for (int t = 0; t < PP; t++) {
        const float* hin = (t == 0) ? h0 : ((t & 1) ? g_hA : g_hB);
        float* hout = (t & 1) ? g_hB : g_hA;

        // whole 32x256 activation tile -> smem (float4 .cg, coalesced)
#pragma unroll
        for (int p = 0; p < 8; p++) {
            int l = tid + p * 256;
            int row = l >> 6, c4 = (l & 63) << 2;
            float4 v = ldcg4(&hin[(r0 + row) * HH + c4]);
            *(float4*)&At[row * ASTRIDE + c4] = v;
        }
        __syncthreads();

        u64t acc2[32];   // [g*8+r], k-pair lane sums over this thread's k-half
#pragma unroll
        for (int j = 0; j < 32; j++) acc2[j] = 0ull;

#pragma unroll 4
        for (int kk = 0; kk < 128; kk += 4) {
            float4 a4[8];
#pragma unroll
            for (int r = 0; r < 8; r++)
                a4[r] = *(const float4*)&At[(rh * 8 + r) * ASTRIDE + kbase + kk];
#pragma unroll
            for (int p = 0; p < 2; p++) {
#pragma unroll
                for (int g = 0; g < 4; g++) {
                    u64t w2 = *(const u64t*)(wrow + g * WGSZ + kbase + kk + 2 * p);
#pragma unroll
                    for (int r = 0; r < 8; r++) {
                        u64t a2 = ((const u64t*)&a4[r])[p];
                        FFMA2(acc2[g * 8 + r], a2, w2);
                    }
                }
            }
        }

        // k-half reduction: kh=1 stores (xor-swizzled, conflict-free), kh=0 accumulates
        __syncthreads();
        {
            u64t* red = (u64t*)At;
            int idx = rh * 32 + tx;
            if (kh == 1) {
#pragma unroll
                for (int j = 0; j < 32; j++)
                    red[(size_t)idx * 32 + (j ^ tx)] = acc2[j];
            }
        }
        __syncthreads();

        if (kh == 0) {
            u64t* red = (u64t*)At;
            int idx = rh * 32 + tx;
#pragma unroll
            for (int j = 0; j < 32; j++) {
                u64t o = red[(size_t)idx * 32 + (j ^ tx)];
                ADD2(acc2[j], o);
            }
#pragma unroll
            for (int r = 0; r < 8; r++) {
                float lo, hi;
                UNPACK2(lo, hi, acc2[0 * 8 + r]); float vi = lo + hi;
                UNPACK2(lo, hi, acc2[1 * 8 + r]); float vf = lo + hi;
                UNPACK2(lo, hi, acc2[2 * 8 + r]); float vg = lo + hi;
                UNPACK2(lo, hi, acc2[3 * 8 + r]); float vo = lo + hi;
                int R = r0 + rh * 8 + r;
                float ig = sigm(vi + gx0[r]);
                float fg = sigm(vf + gx1[r]);
                float gg = tanhf(vg + gx2[r]);
                float og = sigm(vo + gx3[r]);
                float cnew = fg * c_reg[r] + ig * gg;
                float hnew = og * tanhf(cnew);
                bool valid = t < pl[r];
                float cv = valid ? cnew : c_reg[r];
                float hv = valid ? hnew : h_reg[r];
                c_reg[r] = cv;
                h_reg[r] = hv;
                __stcg(&hout[R * HH + u], hv);
            }
        }

        unsigned int a = bar_arrive(&g_bar_lstm[ry]);
        if (kh == 0 && t + 1 < PP) {
#pragma unroll
            for (int r = 0; r < 8; r++) {
                int R = r0 + rh * 8 + r;
                int tok = program[R * PP + t + 1];
                const float* gp = g_encT + (size_t)tok * (4 * HH) + u;
                gx0[r] = __ldg(gp); gx1[r] = __ldg(gp + HH);
                gx2[r] = __ldg(gp + 2 * HH); gx3[r] = __ldg(gp + 3 * HH);
            }
        }
        bar_wait(&g_bar_lstm[ry], 8u, a);
    }
}

// ---------------- persistent GRU: k-split, 2-level barrier, gathers under barrier skew ----------------
__global__ __launch_bounds__(256, 1) void gru_persist(const float* __restrict__ Whh,
                                                      const float* __restrict__ bhh,
                                                      const float* __restrict__ gamma,
                                                      const float* __restrict__ beta,
                                                      const int* __restrict__ trace,
                                                      const int* __restrict__ choices,
                                                      const float* __restrict__ hdec0) {
    extern __shared__ float sm[];
    float* Wsh = sm;                        // [3][32][WSTRIDE] = 24768
    float* At = sm + 3 * WGSZ;              // [32][ASTRIDE] = 8320; also reduce buf
    float* s_sc = At + 32 * ASTRIDE;        // [256]
    float* s_sh = s_sc + HH;                // [256]
    float* psbuf = s_sh + HH;               // [256]

    int tid = threadIdx.x;
    int tx = tid & 31;
    int ty = tid >> 5;
    int rh = ty & 3;
    int kh = ty >> 2;
    int u0 = (blockIdx.x & 7) * 32;
    int ry = blockIdx.x >> 3;
    int r0 = ry * 32;
    int u = u0 + tx;

    for (int idx = tid; idx < 3 * 32 * 256; idx += 256) {
        int k = idx & 255;
        int uu = (idx >> 8) & 31;
        int g = idx >> 13;
        Wsh[g * WGSZ + uu * WSTRIDE + k] = Whh[(g * HH + u0 + uu) * HH + k];
    }

    float bh0 = bhh[u], bh1 = bhh[HH + u], bh2 = bhh[2 * HH + u];
    float gmv = gamma[tid], btv = beta[tid];

    float h_reg[8];
    if (kh == 0) {
#pragma unroll
        for (int r = 0; r < 8; r++) h_reg[r] = hdec0[(r0 + rh * 8 + r) * HH + u];
    }
    __syncthreads();

    const float* wrow = Wsh + tx * WSTRIDE;
    const int kbase = kh * 128;

    // t=0 routed-table gathers (later steps prefetch between arrive & wait)
    float gxr[8], gxz[8], gxn[8];
    if (kh == 0) {
#pragma unroll
        for (int r = 0; r < 8; r++) {
            int R = r0 + rh * 8 + r;
            int prev = trace[R * TT + 0];
            int val = choices[R * NCC + prev];
            const float* pw = g_progW + (size_t)R * (3 * HH) + u;
            const float* iw = g_idxT + (size_t)prev * (3 * HH) + u;
            const float* cw = g_chT + (size_t)(prev * NOO + val) * (3 * HH) + u;
            gxr[0 + r] = __ldg(pw) + __ldg(iw) + __ldg(cw);
            gxz[0 + r] = __ldg(pw + HH) + __ldg(iw + HH) + __ldg(cw + HH);
            gxn[0 + r] = __ldg(pw + 2 * HH) + __ldg(iw + 2 * HH) + __ldg(cw + 2 * HH);
        }
    }

    unsigned int my_round = 0;

    for (int t = 0; t < TT - 1; t++) {
        if (t > 0) glob_wait(my_round);   // psums + h of step t-1 globally visible

        const float* hin = (t == 0) ? hdec0 : (g_hall + (size_t)(t - 1) * BB * HH);
        float* hout = g_hall + (size_t)t * BB * HH;

        // BN scale/shift from step-t partial sums (feature = tid, 64b paired loads)
        {
            float s = 0.f, s2 = 0.f;
#pragma unroll
            for (int p = 0; p < 16; p++) {
                float2 pv = ldcg2(&g_psums[((t * 16 + p) * HH + tid) * 2]);
                s += pv.x; s2 += pv.y;
            }
            float mean = s * (1.f / (float)BB);
            float var = fmaxf(s2 * (1.f / (float)BB) - mean * mean, 0.f);
            float inv = rsqrtf(var + BN_EPS);
            float scv = gmv * inv;
            s_sc[tid] = scv;
            s_sh[tid] = btv - mean * scv;
        }
        __syncthreads();

        // whole 32x256 tile, BN applied inline (L1-bypass loads)
#pragma unroll
        for (int p = 0; p < 8; p++) {
            int l = tid + p * 256;
            int row = l >> 6, c4 = (l & 63) << 2;
            float4 v = ldcg4(&hin[(r0 + row) * HH + c4]);
            v.x = v.x * s_sc[c4 + 0] + s_sh[c4 + 0];
            v.y = v.y * s_sc[c4 + 1] + s_sh[c4 + 1];
            v.z = v.z * s_sc[c4 + 2] + s_sh[c4 + 2];
            v.w = v.w * s_sc[c4 + 3] + s_sh[c4 + 3];
            *(float4*)&At[row * ASTRIDE + c4] = v;
        }
        __syncthreads();

        u64t acc2[24];   // [g*8+r]
#pragma unroll
        for (int j = 0; j < 24; j++) acc2[j] = 0ull;

#pragma unroll 4
        for (int kk = 0; kk < 128; kk += 4) {
            float4 a4[8];
#pragma unroll
            for (int r = 0; r < 8; r++)
                a4[r] = *(const float4*)&At[(rh * 8 + r) * ASTRIDE + kbase + kk];
#pragma unroll
            for (int p = 0; p < 2; p++) {
#pragma unroll
                for (int g = 0; g < 3; g++) {
                    u64t w2 = *(const u64t*)(wrow + g * WGSZ + kbase + kk + 2 * p);
#pragma unroll
                    for (int r = 0; r < 8; r++) {
                        u64t a2 = ((const u64t*)&a4[r])[p];
                        FFMA2(acc2[g * 8 + r], a2, w2);
                    }
                }
            }
        }

        __syncthreads();
        {
            u64t* red = (u64t*)At;
            int idx = rh * 32 + tx;
            if (kh == 1) {
#pragma unroll
                for (int j = 0; j < 24; j++)
                    red[(size_t)idx * 32 + (j ^ tx)] = acc2[j];
            }
        }
        __syncthreads();

        if (kh == 0) {
            u64t* red = (u64t*)At;
            int idx = rh * 32 + tx;
#pragma unroll
            for (int j = 0; j < 24; j++) {
                u64t o = red[(size_t)idx * 32 + (j ^ tx)];
                ADD2(acc2[j], o);
            }
            float scu = s_sc[u], shu = s_sh[u];
            float ps = 0.f, ps2 = 0.f;
#pragma unroll
            for (int r = 0; r < 8; r++) {
                float lo, hi;
                UNPACK2(lo, hi, acc2[0 * 8 + r]); float vr = lo + hi;
                UNPACK2(lo, hi, acc2[1 * 8 + r]); float vz = lo + hi;
                UNPACK2(lo, hi, acc2[2 * 8 + r]); float vn = lo + hi;
                int R = r0 + rh * 8 + r;
                float rr = sigm(gxr[r] + vr + bh0);
                float zz = sigm(gxz[r] + vz + bh1);
                float nn = tanhf(gxn[r] + rr * (vn + bh2));
                float hnb = h_reg[r] * scu + shu;
                float hnew = (1.f - zz) * nn + zz * hnb;
                h_reg[r] = hnew;
                __stcg(&hout[R * HH + u], hnew);
                ps += hnew;
                ps2 += hnew * hnew;
            }
            psbuf[rh * 32 + tx] = ps;
            psbuf[128 + rh * 32 + tx] = ps2;
        }

        // deterministic BN partials for step t+1
        __syncthreads();
        if (ty == 0) {
            float s  = psbuf[tx] + psbuf[32 + tx] + psbuf[64 + tx] + psbuf[96 + tx];
            float s2 = psbuf[128 + tx] + psbuf[160 + tx] + psbuf[192 + tx] + psbuf[224 + tx];
            float2 pv = make_float2(s, s2);
            __stcg(reinterpret_cast<float2*>(&g_psums[(((t + 1) * 16 + ry) * HH + u) * 2]), pv);
        }

        my_round = glob_arrive(ry);

        // prefetch next step's gathers while other groups arrive (hidden latency)
        if (kh == 0 && t + 1 < TT - 1) {
#pragma unroll
            for (int r = 0; r < 8; r++) {
                int R = r0 + rh * 8 + r;
                int prev = trace[R * TT + t + 1];
                int val = choices[R * NCC + prev];
                const float* pw = g_progW + (size_t)R * (3 * HH) + u;
                const float* iw = g_idxT + (size_t)prev * (3 * HH) + u;
                const float* cw = g_chT + (size_t)(prev * NOO + val) * (3 * HH) + u;
                gxr[r] = __ldg(pw) + __ldg(iw) + __ldg(cw);
                gxz[r] = __ldg(pw + HH) + __ldg(iw + HH) + __ldg(cw + HH);
                gxn[r] = __ldg(pw + 2 * HH) + __ldg(iw + 2 * HH) + __ldg(cw + 2 * HH);
            }
        }
    }
}

// ---------------- head binning (coalesced: i = b*127 + t, lanes walk t) ----------------
__global__ __launch_bounds__(256) void count_kernel(const int* __restrict__ trace) {
    int i = blockIdx.x * 256 + threadIdx.x;
    if (i >= NITEMS) return;
    int b = i / (TT - 1), t = i - b * (TT - 1);
    int c = trace[b * TT + t + 1];
    if (c != 0) atomicAdd(&g_counts[c], 1);
}

__global__ void prefix_kernel() {
    if (threadIdx.x == 0) {
        int off = 0;
        for (int c = 0; c < NCC; c++) {
            g_offs[c] = off;
            off += ((g_counts[c] + HEAD_ITEMS - 1) / HEAD_ITEMS) * HEAD_ITEMS;
        }
    }
}

__global__ __launch_bounds__(256) void scatter_kernel(const int* __restrict__ trace) {
    int i = blockIdx.x * 256 + threadIdx.x;
    if (i >= NITEMS) return;
    int b = i / (TT - 1), t = i - b * (TT - 1);
    int c = trace[b * TT + t + 1];
    if (c != 0) {
        int pos = g_offs[c] + atomicAdd(&g_curs[c], 1);
        g_items[pos] = (t << 16) | b;
    }
}

// ---------------- routed head: 32 items per block share one 256x256 W (k-pair f32x2) ----------------
__global__ __launch_bounds__(256) void head_kernel(const int* __restrict__ trace,
                                                   const float* __restrict__ infW,
                                                   const float* __restrict__ infB,
                                                   float* __restrict__ out) {
    __shared__ int sIt[HEAD_ITEMS];
    __shared__ float Hs[HEAD_ITEMS][32];
    __shared__ float Ws[256 * 34];
    int tid = threadIdx.x;
    if (tid < HEAD_ITEMS) sIt[tid] = g_items[blockIdx.x * HEAD_ITEMS + tid];
    __syncthreads();
    int it0 = sIt[0];
    if (it0 < 0) return;
    int t0 = it0 >> 16, b0 = it0 & 0xFFFF;
    int c = trace[b0 * TT + t0 + 1];
    const float* W = infW + (size_t)c * NOO * HH;

    u64t acc2[HEAD_ITEMS];
#pragma unroll
    for (int i = 0; i < HEAD_ITEMS; i++) acc2[i] = 0ull;
    int o = tid;
    const float* wrow = Ws + o * 34;

    for (int k0 = 0; k0 < HH; k0 += 32) {
        for (int l = tid; l < HEAD_ITEMS * 32; l += 256) {
            int i = l >> 5, kk = l & 31;
            int it = sIt[i];
            float v = 0.f;
            if (it >= 0) {
                int tt = it >> 16, bb = it & 0xFFFF;
                v = g_hall[((size_t)tt * BB + bb) * HH + k0 + kk];
            }
            Hs[i][kk] = v;
        }
#pragma unroll 8
        for (int l = tid; l < 8192; l += 256) {
            int oo = l >> 5, kk = l & 31;
            Ws[oo * 34 + kk] = W[oo * HH + k0 + kk];
        }
        __syncthreads();
#pragma unroll
        for (int kk = 0; kk < 32; kk += 2) {
            u64t w2 = *(const u64t*)(wrow + kk);
#pragma unroll
            for (int i = 0; i < HEAD_ITEMS; i++) {
                u64t h2 = *(const u64t*)&Hs[i][kk];
                FFMA2(acc2[i], h2, w2);
            }
        }
        __syncthreads();
    }

    float bias = infB[c * NOO + o];
#pragma unroll
    for (int i = 0; i < HEAD_ITEMS; i++) {
        int it = sIt[i];
        if (it >= 0) {
            float lo, hi;
            UNPACK2(lo, hi, acc2[i]);
            int tt = it >> 16, bb = it & 0xFFFF;
            out[((size_t)tt * BB + bb) * NOO + o] = lo + hi + bias;
        }
    }
}

// ---------------- launcher (lstm_persist at OUR #4: profiled launch = ours+2 offset) ----------------
extern "C" void kernel_launch(void* const* d_in, const int* in_sizes, int n_in,
                              void* d_out, int out_size) {
    const int* program      = (const int*)d_in[0];
    const int* plen         = (const int*)d_in[1];
    const int* trace        = (const int*)d_in[2];
    const int* choices      = (const int*)d_in[3];
    const float* enc_embed  = (const float*)d_in[4];
    const float* lstm_W_ih  = (const float*)d_in[5];
    const float* lstm_W_hh  = (const float*)d_in[6];
    const float* lstm_b_ih  = (const float*)d_in[7];
    const float* lstm_b_hh  = (const float*)d_in[8];
    const float* h0         = (const float*)d_in[9];
    const float* c0         = (const float*)d_in[10];
    const float* index_embed= (const float*)d_in[11];
    const float* choice_tab = (const float*)d_in[12];
    const float* gru_W_ih   = (const float*)d_in[13];
    const float* gru_W_hh   = (const float*)d_in[14];
    const float* gru_b_ih   = (const float*)d_in[15];
    const float* gru_b_hh   = (const float*)d_in[16];
    const float* bn_gamma   = (const float*)d_in[17];
    const float* bn_beta    = (const float*)d_in[18];
    const float* inf_W      = (const float*)d_in[19];
    const float* inf_b      = (const float*)d_in[20];
    const float* h_dec0     = (const float*)d_in[21];
    float* out = (float*)d_out;

    const int LSTM_SMEM = (4 * WGSZ + 32 * ASTRIDE) * 4;                      // 165376 B
    const int GRU_SMEM  = (3 * WGSZ + 32 * ASTRIDE + 2 * HH + 256) * 4;       // 135424 B
    cudaFuncSetAttribute(lstm_persist, cudaFuncAttributeMaxDynamicSharedMemorySize, LSTM_SMEM);
    cudaFuncSetAttribute(gru_persist, cudaFuncAttributeMaxDynamicSharedMemorySize, GRU_SMEM);

    init_kernel<<<4096, 256>>>(out, out_size);                                     // 1
    stats0_kernel<<<16, 256>>>(h_dec0);                                            // 2

    gemm_nt<<<dim3(16, 157), 256>>>(enc_embed, EE, lstm_W_ih, EE,
                                    lstm_b_ih, lstm_b_hh, VV, 4 * HH, EE, 0, 0);   // 3: encT

    lstm_persist<<<NBLK, 256, LSTM_SMEM>>>(lstm_W_hh, program, plen, h0, c0);      // 4 (ncu target)

    gemm_nt<<<dim3(12, 256), 256>>>(choice_tab, EE, gru_W_ih, HH + 2 * EE,
                                    nullptr, nullptr, NCC * NOO, 3 * HH, EE, 1, 0);// 5: chT
    gemm_nt<<<dim3(12, 1), 256>>>(index_embed, EE, gru_W_ih + (HH + EE), HH + 2 * EE,
                                  nullptr, nullptr, NCC, 3 * HH, EE, 2, 0);        // 6: idxT
    gemm_nt<<<dim3(12, 8), 256>>>(nullptr, HH, gru_W_ih + EE, HH + 2 * EE,
                                  gru_b_ih, nullptr, BB, 3 * HH, HH, 3, 1);        // 7: progW

    count_kernel<<<(NITEMS + 255) / 256, 256>>>(trace);                            // 8
    prefix_kernel<<<1, 32>>>();                                                    // 9
    scatter_kernel<<<(NITEMS + 255) / 256, 256>>>(trace);                          // 10

    gru_persist<<<NBLK, 256, GRU_SMEM>>>(gru_W_hh, gru_b_hh, bn_gamma, bn_beta,
                                         trace, choices, h_dec0);                  // 11

    head_kernel<<<ITEM_CAP / HEAD_ITEMS, 256>>>(trace, inf_W, inf_b, out);         // 12
}